// round 5
// baseline (speedup 1.0000x reference)
#include <cuda_runtime.h>
#include <math.h>

#define NN 2048          // nodes
#define MM 512           // groups
#define DD 32            // per-manifold dim
#define CAP 256          // member cache capacity in k_agg1
#define PT 257           // padded stride for agg1 transposed cache
#define CAP2 72          // member cache capacity per row in k_agg2
#define ST2 73           // padded stride for agg2 transposed cache
#define BK 256           // k_agg1 block size (8 warps)
#define FULL 0xffffffffu

// grid-role split for fused pre kernel
#define ROWB_BLOCKS 256  // 8 rows/block (warp per row): rowbits + colbits atomics
#define TRF_BLOCKS 256   // 8 rows/block: per-node transform
#define PRE_BLOCKS (ROWB_BLOCKS + TRF_BLOCKS)

// ---------------- device scratch (no allocs allowed) ----------------
__device__ float g_xs[NN*DD], g_xe[NN*DD];
__device__ float g_lamx[NN*DD];
__device__ float g_lamm1[NN];
__device__ float g_xsn2[NN];

__device__ unsigned g_rowbits[NN*16];   // H row bitmasks (512 bits/row)
__device__ unsigned g_colbits[MM*64];   // H column bitmasks (2048 bits/col); zero-init,
                                        // re-zeroed by k_agg1 after use each run

__device__ float g_es[MM*DD], g_ee[MM*DD];
__device__ float g_elamx[MM*DD];
__device__ float g_elamm1[MM];
__device__ float g_esn2[MM];

// ---------------- helpers ----------------
__device__ __forceinline__ float wsum(float v) {
    #pragma unroll
    for (int o = 16; o; o >>= 1) v += __shfl_xor_sync(FULL, v, o);
    return v;
}
__device__ __forceinline__ float clip1(float v) {
    return fminf(fmaxf(v, -1.0f + 1e-6f), 1.0f - 1e-6f);
}

// ---------------- fused pre kernel: bitmasks | transform by block range ----
__global__ __launch_bounds__(256) void k_pre(const float* __restrict__ x,
                          const float* __restrict__ H,
                          const float* __restrict__ Wh, const float* __restrict__ bh,
                          const float* __restrict__ Ws, const float* __restrict__ bs,
                          const float* __restrict__ We, const float* __restrict__ be,
                          const float* __restrict__ cph) {
    int b = blockIdx.x;
    int lane = threadIdx.x & 31;
    if (b < ROWB_BLOCKS) {
        // ---- bitmask build: warp per row, 16 independent loads up front ----
        int row = b * 8 + (threadIdx.x >> 5);
        const float* rp = H + (size_t)row * MM;
        float h[16];
        #pragma unroll
        for (int j = 0; j < 16; j++) h[j] = rp[j * 32 + lane];   // MLP 16
        unsigned rb = 1u << (row & 31);
        int widx = row >> 5;
        #pragma unroll
        for (int j = 0; j < 16; j++) {
            bool pred = h[j] > 0.5f;
            unsigned m = __ballot_sync(FULL, pred);
            if (lane == 0) g_rowbits[row * 16 + j] = m;
            if (pred) atomicOr(&g_colbits[(j * 32 + lane) * 64 + widx], rb);
        }
        return;
    }
    // ---- transform: warp per row, 8 rows/block ----
    __shared__ float sW[3 * DD * DD];
    __shared__ float sB[3 * DD];
    for (int i = threadIdx.x; i < DD * DD; i += blockDim.x) {
        sW[i]             = Wh[i];
        sW[DD*DD + i]     = Ws[i];
        sW[2*DD*DD + i]   = We[i];
    }
    if (threadIdx.x < DD) {
        sB[threadIdx.x]        = bh[threadIdx.x];
        sB[DD + threadIdx.x]   = bs[threadIdx.x];
        sB[2*DD + threadIdx.x] = be[threadIdx.x];
    }
    __syncthreads();

    int r = (b - ROWB_BLOCKS) * 8 + (threadIdx.x >> 5);

    float c  = fabsf(*cph) + 1e-6f;
    float sc = sqrtf(c);
    float maxn = (1.0f - 1e-5f) / sc;

    float xh = x[r * 96 + lane];
    float xs = x[r * 96 + 32 + lane];
    float xe = x[r * 96 + 64 + lane];

    // hyp_project(x_h)
    float n  = sqrtf(wsum(xh * xh));
    float nm = fmaxf(n, 1e-6f);
    if (nm > maxn) xh *= maxn / nm;

    // logmap0
    n = fmaxf(sqrtf(wsum(xh * xh)), 1e-6f);
    float arg = clip1(sc * n);
    float lg  = atanhf(arg) * xh / (sc * n);

    // v = lg @ Wh^T + bh
    float v = sB[lane];
    #pragma unroll
    for (int i = 0; i < DD; i++)
        v = fmaf(__shfl_sync(FULL, lg, i), sW[lane * DD + i], v);

    // expmap0
    n = fmaxf(sqrtf(wsum(v * v)), 1e-6f);
    float xh2 = tanhf(sc * n) * v / (sc * n);
    // hyp_project
    n  = sqrtf(wsum(xh2 * xh2));
    nm = fmaxf(n, 1e-6f);
    if (nm > maxn) xh2 *= maxn / nm;

    float sq  = wsum(xh2 * xh2);
    float lam = 2.0f / fmaxf(1.0f - c * sq, 1e-6f);
    g_lamx[r * DD + lane] = lam * xh2;
    if (lane == 0) g_lamm1[r] = lam - 1.0f;

    // sphere branch
    n = fmaxf(sqrtf(wsum(xs * xs)), 1e-6f);
    xs /= n;
    float s2 = sB[DD + lane];
    #pragma unroll
    for (int i = 0; i < DD; i++)
        s2 = fmaf(__shfl_sync(FULL, xs, i), sW[DD*DD + lane * DD + i], s2);
    n = fmaxf(sqrtf(wsum(s2 * s2)), 1e-6f);
    s2 /= n;
    g_xs[r * DD + lane] = s2;
    float pn = wsum(s2 * s2);
    if (lane == 0) g_xsn2[r] = pn;

    // euclidean branch
    float e2 = sB[2*DD + lane];
    #pragma unroll
    for (int i = 0; i < DD; i++)
        e2 = fmaf(__shfl_sync(FULL, xe, i), sW[2*DD*DD + lane * DD + i], e2);
    g_xe[r * DD + lane] = e2;
}

// ---------------- stage 1: nodes -> 512 groups (block per group) ----------------
__global__ __launch_bounds__(BK) void k_agg1(const float* __restrict__ cph) {
    __shared__ float s_pT[DD * PT];     // transposed points [d][m]
    __shared__ float s_pp[CAP];
    __shared__ float s_a[CAP];
    __shared__ float s_ad[CAP];         // a * dotc
    __shared__ float s_ar[CAP];         // a * draw
    __shared__ float s_mu[DD];
    __shared__ float s_vec[8][3][DD];
    __shared__ float s_sc[8];
    __shared__ float s_tw[8][DD];
    __shared__ float s_bw[8];
    __shared__ float s_brw[8];
    __shared__ unsigned s_cw[64];
    __shared__ int s_woff[64];
    __shared__ int s_list[CAP];
    __shared__ int s_tot;

    int g    = blockIdx.x;
    int w    = threadIdx.x >> 5;
    int lane = threadIdx.x & 31;
    int tid  = threadIdx.x;

    float c  = fabsf(*cph) + 1e-6f;
    float sc = sqrtf(c);

    // ---- decode column bitmask into compact member list ----
    if (tid < 64) s_cw[tid] = g_colbits[g * 64 + tid];
    __syncthreads();
    if (w == 0) {
        int c0 = __popc(s_cw[2 * lane]);
        int c1 = __popc(s_cw[2 * lane + 1]);
        int s = c0 + c1;
        int incl = s;
        #pragma unroll
        for (int o = 1; o < 32; o <<= 1) {
            int vv = __shfl_up_sync(FULL, incl, o);
            if (lane >= o) incl += vv;
        }
        int excl = incl - s;
        s_woff[2 * lane]     = excl;
        s_woff[2 * lane + 1] = excl + c0;
        if (lane == 31) s_tot = incl;
    }
    __syncthreads();
    int tot = s_tot;
    bool cache = (tot <= CAP);
    float cntf = (float)tot;

    if (cache && tid < 64) {
        unsigned word = s_cw[tid];
        int off  = s_woff[tid];
        int base = tid * 32;
        while (word) {
            s_list[off++] = base + __ffs(word) - 1;
            word &= word - 1;
        }
    }
    // reset colbits for the next run (this block owns column g)
    if (tid < 64) g_colbits[g * 64 + tid] = 0;
    __syncthreads();

    // ---- phase A: linear sums + transposed SMEM member cache ----
    float sp = 0.f, sl = 0.f, se = 0.f, sm = 0.f;
    if (cache) {
        for (int m = w; m < tot; m += 8) {
            int k = s_list[m];
            float p = g_xs[k * DD + lane];
            sp += p;
            sl += g_lamx[k * DD + lane];
            se += g_xe[k * DD + lane];
            sm += g_lamm1[k];
            s_pT[lane * PT + m] = p;
            if (lane == 0) s_pp[m] = g_xsn2[k];
        }
    } else {
        for (int wd = w; wd < 64; wd += 8) {
            unsigned word = s_cw[wd];
            while (word) {
                int k = wd * 32 + __ffs(word) - 1;
                word &= word - 1;
                sp += g_xs[k * DD + lane];
                sl += g_lamx[k * DD + lane];
                se += g_xe[k * DD + lane];
                sm += g_lamm1[k];
            }
        }
    }
    s_vec[w][0][lane] = sp;
    s_vec[w][1][lane] = sl;
    s_vec[w][2][lane] = se;
    if (lane == 0) s_sc[w] = sm;
    __syncthreads();

    if (w == 0) {
        float tp = 0.f, tl = 0.f, te = 0.f, tm = 0.f;
        #pragma unroll
        for (int u = 0; u < 8; u++) {
            tp += s_vec[u][0][lane];
            tl += s_vec[u][1][lane];
            te += s_vec[u][2][lane];
            tm += s_sc[u];
        }
        g_ee[g * DD + lane] = te / fmaxf(cntf, 1e-6f);

        // gyromidpoint
        float den = fmaxf(tm, 1e-6f);
        float y   = tl / den;
        float yn  = fmaxf(sqrtf(wsum(y * y)), 1e-6f);
        float arg = clip1(sc * yn);
        float eh  = tanhf(0.5f * atanhf(arg)) * y / (sc * yn);
        float sq  = wsum(eh * eh);
        float lam = 2.0f / fmaxf(1.0f - c * sq, 1e-6f);
        g_elamx[g * DD + lane] = lam * eh;
        if (lane == 0) g_elamm1[g] = lam - 1.0f;

        // sphere mu0 (unit norm => mm == 1 henceforth)
        float mu = tp / cntf;
        mu /= fmaxf(sqrtf(wsum(mu * mu)), 1e-6f);
        s_mu[lane] = mu;
    }
    __syncthreads();

    // ---- phase B: 5 Frechet iterations ----
    for (int it = 0; it < 5; it++) {
        if (cache) {
            // (1) member-per-thread dots
            for (int m = tid; m < tot; m += BK) {
                float d0 = 0.f, d1 = 0.f;
                #pragma unroll
                for (int d = 0; d < DD; d += 2) {
                    d0 = fmaf(s_mu[d],     s_pT[d * PT + m],       d0);
                    d1 = fmaf(s_mu[d + 1], s_pT[(d + 1) * PT + m], d1);
                }
                float draw = d0 + d1;
                float dotc = clip1(draw);
                float theta = acosf(dotc);
                float dn2 = s_pp[m] - dotc * (2.0f * draw - dotc);   // mm = 1
                float dn  = fmaxf(sqrtf(fmaxf(dn2, 0.f)), 1e-6f);
                float a   = theta / dn;
                s_a[m]  = a;
                s_ad[m] = a * dotc;
                s_ar[m] = a * draw;
            }
            __syncthreads();
            // (2) dim-per-lane accumulation, warps stripe members
            float tpart = 0.f, bpart = 0.f, brpart = 0.f;
            for (int m = w; m < tot; m += 8) {
                tpart  = fmaf(s_a[m], s_pT[lane * PT + m], tpart);
                bpart  += s_ad[m];
                brpart += s_ar[m];
            }
            s_tw[w][lane] = tpart;
            if (lane == 0) { s_bw[w] = bpart; s_brw[w] = brpart; }
        } else {
            float mu = s_mu[lane];
            float t = 0.f, bsum = 0.f, brsum = 0.f;
            for (int wd = w; wd < 64; wd += 8) {
                unsigned word = s_cw[wd];
                while (word) {
                    int k = wd * 32 + __ffs(word) - 1;
                    word &= word - 1;
                    float p    = g_xs[k * DD + lane];
                    float draw = wsum(mu * p);
                    float dotc = clip1(draw);
                    float theta = acosf(dotc);
                    float dn2 = g_xsn2[k] - dotc * (2.0f * draw - dotc);
                    float dn  = fmaxf(sqrtf(fmaxf(dn2, 0.f)), 1e-6f);
                    float a   = theta / dn;
                    t     = fmaf(a, p, t);
                    bsum  += a * dotc;
                    brsum += a * draw;
                }
            }
            s_tw[w][lane] = t;
            if (lane == 0) { s_bw[w] = bsum; s_brw[w] = brsum; }
        }
        __syncthreads();
        // (3) epilogue: ALL warps compute identical result (same-value race on s_mu
        //     is benign; no trailing block barrier needed)
        {
            float mu = s_mu[lane];
            float tsum = 0.f, bt = 0.f, br = 0.f;
            #pragma unroll
            for (int u = 0; u < 8; u++) { tsum += s_tw[u][lane]; bt += s_bw[u]; br += s_brw[u]; }
            float t = fmaf(-bt, mu, tsum);
            float avg = t / cntf;
            float vn2 = wsum(avg * avg);                 // only reduction in epilogue
            float vn  = sqrtf(vn2);
            float vns = fmaxf(vn, 1e-6f);
            float cv = cosf(vn), sv = sinf(vn);
            float mudotavg = (br - bt) / cntf;           // mu . avg  (mm = 1)
            float r   = cv * mu + sv * avg / vns;
            float svv = sv / vns;
            float rn2 = fmaf(cv * cv, 1.0f, fmaf(2.0f * cv * svv, mudotavg, svv * svv * vn2));
            float rn  = fmaxf(sqrtf(rn2), 1e-6f);
            s_mu[lane] = r / rn;
            __syncwarp();
        }
        __syncthreads();   // protects s_a rewrite in next iteration's step (1)
    }
    if (w == 0) {
        float mu = s_mu[lane];
        g_es[g * DD + lane] = mu;
        float pn = wsum(mu * mu);
        if (lane == 0) g_esn2[g] = pn;
    }
}

// ---------------- stage 2: groups -> 2048 nodes (warp per row, SMEM cache) ------
__global__ __launch_bounds__(128) void k_agg2(float* __restrict__ out, const float* __restrict__ cph) {
    __shared__ float s_pT[4][DD * ST2];   // per-warp transposed member cache
    __shared__ float s_pp[4][CAP2];
    __shared__ float s_a[4][CAP2];
    __shared__ float s_mu[4][DD];
    __shared__ int   s_lst[4][CAP2];

    int w    = threadIdx.x >> 5;
    int lane = threadIdx.x & 31;
    int i    = blockIdx.x * 4 + w;

    float c  = fabsf(*cph) + 1e-6f;
    float sc = sqrtf(c);
    float maxn = (1.0f - 1e-5f) / sc;

    // ---- decode row bitmask ----
    unsigned myword = (lane < 16) ? g_rowbits[i * 16 + lane] : 0u;
    int pc = __popc(myword);
    int incl = pc;
    #pragma unroll
    for (int o = 1; o < 32; o <<= 1) {
        int vv = __shfl_up_sync(FULL, incl, o);
        if (lane >= o) incl += vv;
    }
    int excl = incl - pc;
    int cnt  = __shfl_sync(FULL, incl, 15);
    bool cache = (cnt <= CAP2);
    float cntf = (float)cnt;

    if (cache && lane < 16) {
        unsigned word = myword;
        int off  = excl;
        int base = lane * 32;
        while (word) {
            s_lst[w][off++] = base + __ffs(word) - 1;
            word &= word - 1;
        }
    }
    __syncwarp();

    // prologue: linear sums + cache
    float sp = 0.f, sl = 0.f, se = 0.f, sm = 0.f;
    if (cache) {
        for (int j = 0; j < cnt; j++) {
            int g = s_lst[w][j];
            float p = g_es[g * DD + lane];
            sp += p;
            sl += g_elamx[g * DD + lane];
            se += g_ee[g * DD + lane];
            sm += g_elamm1[g];
            s_pT[w][lane * ST2 + j] = p;
            if (lane == 0) s_pp[w][j] = g_esn2[g];
        }
    } else {
        for (int wd = 0; wd < 16; wd++) {
            unsigned word = g_rowbits[i * 16 + wd];
            while (word) {
                int g = wd * 32 + __ffs(word) - 1;
                word &= word - 1;
                sp += g_es[g * DD + lane];
                sl += g_elamx[g * DD + lane];
                se += g_ee[g * DD + lane];
                sm += g_elamm1[g];
            }
        }
    }

    float oe = se / fmaxf(cntf, 1e-6f);

    // gyromidpoint + final hyp_project
    float den = fmaxf(sm, 1e-6f);
    float y   = sl / den;
    float yn  = fmaxf(sqrtf(wsum(y * y)), 1e-6f);
    float arg = clip1(sc * yn);
    float oh  = tanhf(0.5f * atanhf(arg)) * y / (sc * yn);
    float n   = sqrtf(wsum(oh * oh));
    float nm  = fmaxf(n, 1e-6f);
    if (nm > maxn) oh *= maxn / nm;

    // sphere midpoint
    float mu = sp / cntf;
    mu /= fmaxf(sqrtf(wsum(mu * mu)), 1e-6f);

    if (cache) {
        s_mu[w][lane] = mu;
        __syncwarp();
        for (int it = 0; it < 5; it++) {
            // (1) lane = member: dots, no shuffles
            float asum_d = 0.f, asum_r = 0.f;
            for (int m = lane; m < cnt; m += 32) {
                float d0 = 0.f, d1 = 0.f;
                #pragma unroll
                for (int d = 0; d < DD; d += 2) {
                    d0 = fmaf(s_mu[w][d],     s_pT[w][d * ST2 + m],       d0);
                    d1 = fmaf(s_mu[w][d + 1], s_pT[w][(d + 1) * ST2 + m], d1);
                }
                float draw = d0 + d1;
                float dotc = clip1(draw);
                float theta = acosf(dotc);
                float dn2 = s_pp[w][m] - dotc * (2.0f * draw - dotc);  // mm = 1
                float dn  = fmaxf(sqrtf(fmaxf(dn2, 0.f)), 1e-6f);
                float a   = theta / dn;
                s_a[w][m] = a;
                asum_d = fmaf(a, dotc, asum_d);
                asum_r = fmaf(a, draw, asum_r);
            }
            __syncwarp();
            float bt = wsum(asum_d);
            float br = wsum(asum_r);
            // (2) lane = dim accumulation
            float t0 = 0.f, t1 = 0.f;
            int m = 0;
            for (; m + 1 < cnt; m += 2) {
                t0 = fmaf(s_a[w][m],     s_pT[w][lane * ST2 + m],     t0);
                t1 = fmaf(s_a[w][m + 1], s_pT[w][lane * ST2 + m + 1], t1);
            }
            if (m < cnt) t0 = fmaf(s_a[w][m], s_pT[w][lane * ST2 + m], t0);
            float mul = s_mu[w][lane];
            float t = fmaf(-bt, mul, t0 + t1);
            float avg = t / cntf;
            float vn2 = wsum(avg * avg);
            float vn  = sqrtf(vn2);
            float vns = fmaxf(vn, 1e-6f);
            float cv = cosf(vn), sv = sinf(vn);
            float mudotavg = (br - bt) / cntf;
            float r   = cv * mul + sv * avg / vns;
            float svv = sv / vns;
            float rn2 = fmaf(cv * cv, 1.0f, fmaf(2.0f * cv * svv, mudotavg, svv * svv * vn2));
            float rn  = fmaxf(sqrtf(rn2), 1e-6f);
            mul = r / rn;
            s_mu[w][lane] = mul;
            __syncwarp();
        }
        mu = s_mu[w][lane];
    } else {
        // fallback: shuffle-based path over row bits (rare)
        for (int it = 0; it < 5; it++) {
            float mm = wsum(mu * mu);
            float t = 0.f, bsum = 0.f;
            for (int wd = 0; wd < 16; wd++) {
                unsigned word = g_rowbits[i * 16 + wd];
                while (word) {
                    int g0 = wd * 32 + __ffs(word) - 1;
                    word &= word - 1;
                    float p0 = g_es[g0 * DD + lane];
                    float w0 = wsum(mu * p0);
                    float dc0 = clip1(w0);
                    float th0 = acosf(dc0);
                    float q0 = g_esn2[g0] - dc0 * (2.0f * w0 - dc0 * mm);
                    float a0 = th0 / fmaxf(sqrtf(fmaxf(q0, 0.f)), 1e-6f);
                    t    = fmaf(a0, p0, t);
                    bsum = fmaf(-a0, dc0, bsum);
                }
            }
            t = fmaf(bsum, mu, t);
            t /= cntf;
            float vn  = sqrtf(wsum(t * t));
            float vns = fmaxf(vn, 1e-6f);
            mu = cosf(vn) * mu + sinf(vn) * t / vns;
            mu /= fmaxf(sqrtf(wsum(mu * mu)), 1e-6f);
        }
    }
    float os = mu / fmaxf(sqrtf(wsum(mu * mu)), 1e-6f);

    out[i * 96 + lane]      = oh;
    out[i * 96 + 32 + lane] = os;
    out[i * 96 + 64 + lane] = oe;
}

// ---------------- launch ----------------
extern "C" void kernel_launch(void* const* d_in, const int* in_sizes, int n_in,
                              void* d_out, int out_size) {
    const float* x   = (const float*)d_in[0];
    const float* H   = (const float*)d_in[1];
    const float* Wh  = (const float*)d_in[2];
    const float* bh  = (const float*)d_in[3];
    const float* Ws  = (const float*)d_in[4];
    const float* bs  = (const float*)d_in[5];
    const float* We  = (const float*)d_in[6];
    const float* be  = (const float*)d_in[7];
    const float* c_h = (const float*)d_in[8];
    float* out = (float*)d_out;

    k_pre<<<PRE_BLOCKS, 256>>>(x, H, Wh, bh, Ws, bs, We, be, c_h);
    k_agg1<<<MM, BK>>>(c_h);
    k_agg2<<<NN / 4, 128>>>(out, c_h);
}

// round 6
// speedup vs baseline: 1.0271x; 1.0271x over previous
#include <cuda_runtime.h>
#include <math.h>

#define NN 2048          // nodes
#define MM 512           // groups
#define DD 32            // per-manifold dim
#define CAP 256          // member cache capacity in k_agg1
#define PT 257           // padded stride for agg1 transposed cache
#define CAP2 72          // member cache capacity per row in k_agg2
#define ST2 73           // padded stride for agg2 transposed cache
#define BK 256           // k_agg1 block size (8 warps)
#define FULL 0xffffffffu

// grid-role split for fused pre kernel
#define HB_BLOCKS 64     // H-bitmask blocks: 32 rows x 512 cols tile each
#define TRF_BLOCKS 256   // 8 rows/block: per-node transform
#define PRE_BLOCKS (HB_BLOCKS + TRF_BLOCKS)

// ---------------- device scratch (no allocs allowed) ----------------
__device__ float g_xs[NN*DD], g_xe[NN*DD];
__device__ float g_lamx[NN*DD];
__device__ float g_lamm1[NN];
__device__ float g_xsn2[NN];

__device__ unsigned g_rowbits[NN*16];   // H row bitmasks (512 bits/row)
__device__ unsigned g_colbits[MM*64];   // H column bitmasks (2048 bits/col), plain stores

__device__ float g_es[MM*DD], g_ee[MM*DD];
__device__ float g_elamx[MM*DD];
__device__ float g_elamm1[MM];
__device__ float g_esn2[MM];

// ---------------- helpers ----------------
__device__ __forceinline__ float wsum(float v) {
    #pragma unroll
    for (int o = 16; o; o >>= 1) v += __shfl_xor_sync(FULL, v, o);
    return v;
}
__device__ __forceinline__ float clip1(float v) {
    return fminf(fmaxf(v, -1.0f + 1e-6f), 1.0f - 1e-6f);
}

// ---------------- fused pre kernel: H-bitmasks | transform by block range ----
__global__ __launch_bounds__(256) void k_pre(const float* __restrict__ x,
                          const float* __restrict__ H,
                          const float* __restrict__ Wh, const float* __restrict__ bh,
                          const float* __restrict__ Ws, const float* __restrict__ bs,
                          const float* __restrict__ We, const float* __restrict__ be,
                          const float* __restrict__ cph) {
    int b = blockIdx.x;
    int lane = threadIdx.x & 31;
    if (b < HB_BLOCKS) {
        // ---- bitmask tile: 32 rows x 512 cols; warp handles 4 rows ----
        __shared__ unsigned s_bits[32][16];
        int w = threadIdx.x >> 5;
        #pragma unroll
        for (int q = 0; q < 4; q++) {
            int rr  = w * 4 + q;            // row within tile
            int row = b * 32 + rr;
            const float* rp = H + (size_t)row * MM;
            float h[16];
            #pragma unroll
            for (int j = 0; j < 16; j++) h[j] = rp[j * 32 + lane];   // MLP 16
            unsigned mymask = 0;
            #pragma unroll
            for (int j = 0; j < 16; j++) {
                unsigned m = __ballot_sync(FULL, h[j] > 0.5f);
                if (lane == j) mymask = m;
            }
            if (lane < 16) {
                s_bits[rr][lane] = mymask;
                g_rowbits[row * 16 + lane] = mymask;
            }
        }
        __syncthreads();
        // ---- transpose 32x512 bit tile: one colbits word per column ----
        #pragma unroll
        for (int gg = 0; gg < 2; gg++) {
            int g  = gg * 256 + threadIdx.x;
            int wi = g >> 5, bi = g & 31;
            unsigned wbits = 0;
            #pragma unroll
            for (int r = 0; r < 32; r++)
                wbits |= ((s_bits[r][wi] >> bi) & 1u) << r;
            g_colbits[g * 64 + b] = wbits;
        }
        return;
    }
    // ---- transform: warp per row, 8 rows/block ----
    __shared__ float sW[3 * DD * DD];
    __shared__ float sB[3 * DD];
    for (int i = threadIdx.x; i < DD * DD; i += blockDim.x) {
        sW[i]             = Wh[i];
        sW[DD*DD + i]     = Ws[i];
        sW[2*DD*DD + i]   = We[i];
    }
    if (threadIdx.x < DD) {
        sB[threadIdx.x]        = bh[threadIdx.x];
        sB[DD + threadIdx.x]   = bs[threadIdx.x];
        sB[2*DD + threadIdx.x] = be[threadIdx.x];
    }
    __syncthreads();

    int r = (b - HB_BLOCKS) * 8 + (threadIdx.x >> 5);

    float c  = fabsf(*cph) + 1e-6f;
    float sc = sqrtf(c);
    float maxn = (1.0f - 1e-5f) / sc;

    float xh = x[r * 96 + lane];
    float xs = x[r * 96 + 32 + lane];
    float xe = x[r * 96 + 64 + lane];

    // hyp_project(x_h)
    float n  = sqrtf(wsum(xh * xh));
    float nm = fmaxf(n, 1e-6f);
    if (nm > maxn) xh *= maxn / nm;

    // logmap0
    n = fmaxf(sqrtf(wsum(xh * xh)), 1e-6f);
    float arg = clip1(sc * n);
    float lg  = atanhf(arg) * xh / (sc * n);

    // v = lg @ Wh^T + bh
    float v = sB[lane];
    #pragma unroll
    for (int i = 0; i < DD; i++)
        v = fmaf(__shfl_sync(FULL, lg, i), sW[lane * DD + i], v);

    // expmap0
    n = fmaxf(sqrtf(wsum(v * v)), 1e-6f);
    float xh2 = tanhf(sc * n) * v / (sc * n);
    // hyp_project
    n  = sqrtf(wsum(xh2 * xh2));
    nm = fmaxf(n, 1e-6f);
    if (nm > maxn) xh2 *= maxn / nm;

    float sq  = wsum(xh2 * xh2);
    float lam = 2.0f / fmaxf(1.0f - c * sq, 1e-6f);
    g_lamx[r * DD + lane] = lam * xh2;
    if (lane == 0) g_lamm1[r] = lam - 1.0f;

    // sphere branch
    n = fmaxf(sqrtf(wsum(xs * xs)), 1e-6f);
    xs /= n;
    float s2 = sB[DD + lane];
    #pragma unroll
    for (int i = 0; i < DD; i++)
        s2 = fmaf(__shfl_sync(FULL, xs, i), sW[DD*DD + lane * DD + i], s2);
    n = fmaxf(sqrtf(wsum(s2 * s2)), 1e-6f);
    s2 /= n;
    g_xs[r * DD + lane] = s2;
    float pn = wsum(s2 * s2);
    if (lane == 0) g_xsn2[r] = pn;

    // euclidean branch
    float e2 = sB[2*DD + lane];
    #pragma unroll
    for (int i = 0; i < DD; i++)
        e2 = fmaf(__shfl_sync(FULL, xe, i), sW[2*DD*DD + lane * DD + i], e2);
    g_xe[r * DD + lane] = e2;
}

// ---------------- stage 1: nodes -> 512 groups (block per group) ----------------
__global__ __launch_bounds__(BK) void k_agg1(const float* __restrict__ cph) {
    __shared__ float s_pT[DD * PT];     // transposed points [d][m]
    __shared__ float s_pp[CAP];
    __shared__ float s_a[CAP];
    __shared__ float s_ad[CAP];         // a * dotc
    __shared__ float s_ar[CAP];         // a * draw
    __shared__ float s_mu[DD];
    __shared__ float s_vec[8][3][DD];
    __shared__ float s_sc[8];
    __shared__ float s_tw[8][DD];
    __shared__ float s_bw[8];
    __shared__ float s_brw[8];
    __shared__ unsigned s_cw[64];
    __shared__ int s_woff[64];
    __shared__ int s_list[CAP];
    __shared__ int s_tot;

    int g    = blockIdx.x;
    int w    = threadIdx.x >> 5;
    int lane = threadIdx.x & 31;
    int tid  = threadIdx.x;

    float c  = fabsf(*cph) + 1e-6f;
    float sc = sqrtf(c);

    // ---- decode column bitmask into compact member list ----
    if (tid < 64) s_cw[tid] = g_colbits[g * 64 + tid];   // coalesced 64-word burst
    __syncthreads();
    if (w == 0) {
        int c0 = __popc(s_cw[2 * lane]);
        int c1 = __popc(s_cw[2 * lane + 1]);
        int s = c0 + c1;
        int incl = s;
        #pragma unroll
        for (int o = 1; o < 32; o <<= 1) {
            int vv = __shfl_up_sync(FULL, incl, o);
            if (lane >= o) incl += vv;
        }
        int excl = incl - s;
        s_woff[2 * lane]     = excl;
        s_woff[2 * lane + 1] = excl + c0;
        if (lane == 31) s_tot = incl;
    }
    __syncthreads();
    int tot = s_tot;
    bool cache = (tot <= CAP);
    float cntf = (float)tot;

    if (cache && tid < 64) {
        unsigned word = s_cw[tid];
        int off  = s_woff[tid];
        int base = tid * 32;
        while (word) {
            s_list[off++] = base + __ffs(word) - 1;
            word &= word - 1;
        }
    }
    __syncthreads();

    // ---- phase A: linear sums + transposed SMEM member cache (2-way ILP) ----
    float sp = 0.f, sl = 0.f, se = 0.f, sm = 0.f;
    if (cache) {
        int m = w;
        for (; m + 8 < tot; m += 16) {
            int k0 = s_list[m], k1 = s_list[m + 8];
            float p0 = g_xs[k0 * DD + lane];
            float p1 = g_xs[k1 * DD + lane];
            float l0 = g_lamx[k0 * DD + lane];
            float l1 = g_lamx[k1 * DD + lane];
            float e0 = g_xe[k0 * DD + lane];
            float e1 = g_xe[k1 * DD + lane];
            sp += p0 + p1;
            sl += l0 + l1;
            se += e0 + e1;
            sm += g_lamm1[k0] + g_lamm1[k1];
            s_pT[lane * PT + m]     = p0;
            s_pT[lane * PT + m + 8] = p1;
            if (lane == 0) { s_pp[m] = g_xsn2[k0]; s_pp[m + 8] = g_xsn2[k1]; }
        }
        if (m < tot) {
            int k = s_list[m];
            float p = g_xs[k * DD + lane];
            sp += p;
            sl += g_lamx[k * DD + lane];
            se += g_xe[k * DD + lane];
            sm += g_lamm1[k];
            s_pT[lane * PT + m] = p;
            if (lane == 0) s_pp[m] = g_xsn2[k];
        }
    } else {
        for (int wd = w; wd < 64; wd += 8) {
            unsigned word = s_cw[wd];
            while (word) {
                int k = wd * 32 + __ffs(word) - 1;
                word &= word - 1;
                sp += g_xs[k * DD + lane];
                sl += g_lamx[k * DD + lane];
                se += g_xe[k * DD + lane];
                sm += g_lamm1[k];
            }
        }
    }
    s_vec[w][0][lane] = sp;
    s_vec[w][1][lane] = sl;
    s_vec[w][2][lane] = se;
    if (lane == 0) s_sc[w] = sm;
    __syncthreads();

    if (w == 0) {
        float tp = 0.f, tl = 0.f, te = 0.f, tm = 0.f;
        #pragma unroll
        for (int u = 0; u < 8; u++) {
            tp += s_vec[u][0][lane];
            tl += s_vec[u][1][lane];
            te += s_vec[u][2][lane];
            tm += s_sc[u];
        }
        g_ee[g * DD + lane] = te / fmaxf(cntf, 1e-6f);

        // gyromidpoint
        float den = fmaxf(tm, 1e-6f);
        float y   = tl / den;
        float yn  = fmaxf(sqrtf(wsum(y * y)), 1e-6f);
        float arg = clip1(sc * yn);
        float eh  = tanhf(0.5f * atanhf(arg)) * y / (sc * yn);
        float sq  = wsum(eh * eh);
        float lam = 2.0f / fmaxf(1.0f - c * sq, 1e-6f);
        g_elamx[g * DD + lane] = lam * eh;
        if (lane == 0) g_elamm1[g] = lam - 1.0f;

        // sphere mu0 (unit norm => mm == 1 henceforth)
        float mu = tp / cntf;
        mu /= fmaxf(sqrtf(wsum(mu * mu)), 1e-6f);
        s_mu[lane] = mu;
    }
    __syncthreads();

    // ---- phase B: 5 Frechet iterations ----
    for (int it = 0; it < 5; it++) {
        if (cache) {
            // (1) member-per-thread dots
            for (int m = tid; m < tot; m += BK) {
                float d0 = 0.f, d1 = 0.f;
                #pragma unroll
                for (int d = 0; d < DD; d += 2) {
                    d0 = fmaf(s_mu[d],     s_pT[d * PT + m],       d0);
                    d1 = fmaf(s_mu[d + 1], s_pT[(d + 1) * PT + m], d1);
                }
                float draw = d0 + d1;
                float dotc = clip1(draw);
                float theta = acosf(dotc);
                float dn2 = s_pp[m] - dotc * (2.0f * draw - dotc);   // mm = 1
                float dn  = fmaxf(sqrtf(fmaxf(dn2, 0.f)), 1e-6f);
                float a   = theta / dn;
                s_a[m]  = a;
                s_ad[m] = a * dotc;
                s_ar[m] = a * draw;
            }
            __syncthreads();
            // (2) dim-per-lane accumulation, warps stripe members
            float tpart = 0.f, bpart = 0.f, brpart = 0.f;
            for (int m = w; m < tot; m += 8) {
                tpart  = fmaf(s_a[m], s_pT[lane * PT + m], tpart);
                bpart  += s_ad[m];
                brpart += s_ar[m];
            }
            s_tw[w][lane] = tpart;
            if (lane == 0) { s_bw[w] = bpart; s_brw[w] = brpart; }
        } else {
            float mu = s_mu[lane];
            float t = 0.f, bsum = 0.f, brsum = 0.f;
            for (int wd = w; wd < 64; wd += 8) {
                unsigned word = s_cw[wd];
                while (word) {
                    int k = wd * 32 + __ffs(word) - 1;
                    word &= word - 1;
                    float p    = g_xs[k * DD + lane];
                    float draw = wsum(mu * p);
                    float dotc = clip1(draw);
                    float theta = acosf(dotc);
                    float dn2 = g_xsn2[k] - dotc * (2.0f * draw - dotc);
                    float dn  = fmaxf(sqrtf(fmaxf(dn2, 0.f)), 1e-6f);
                    float a   = theta / dn;
                    t     = fmaf(a, p, t);
                    bsum  += a * dotc;
                    brsum += a * draw;
                }
            }
            s_tw[w][lane] = t;
            if (lane == 0) { s_bw[w] = bsum; s_brw[w] = brsum; }
        }
        __syncthreads();
        // (3) epilogue: ALL warps compute identical result (same-value race on s_mu)
        {
            float mu = s_mu[lane];
            float tsum = 0.f, bt = 0.f, br = 0.f;
            #pragma unroll
            for (int u = 0; u < 8; u++) { tsum += s_tw[u][lane]; bt += s_bw[u]; br += s_brw[u]; }
            float t = fmaf(-bt, mu, tsum);
            float avg = t / cntf;
            float vn2 = wsum(avg * avg);                 // only reduction in epilogue
            float vn  = sqrtf(vn2);
            float vns = fmaxf(vn, 1e-6f);
            float cv = cosf(vn), sv = sinf(vn);
            float mudotavg = (br - bt) / cntf;           // mu . avg  (mm = 1)
            float r   = cv * mu + sv * avg / vns;
            float svv = sv / vns;
            float rn2 = fmaf(cv * cv, 1.0f, fmaf(2.0f * cv * svv, mudotavg, svv * svv * vn2));
            float rn  = fmaxf(sqrtf(rn2), 1e-6f);
            s_mu[lane] = r / rn;
            __syncwarp();
        }
        __syncthreads();
    }
    if (w == 0) {
        float mu = s_mu[lane];
        g_es[g * DD + lane] = mu;
        float pn = wsum(mu * mu);
        if (lane == 0) g_esn2[g] = pn;
    }
}

// ---------------- stage 2: groups -> 2048 nodes (warp per row, SMEM cache) ------
__global__ __launch_bounds__(128) void k_agg2(float* __restrict__ out, const float* __restrict__ cph) {
    __shared__ float s_pT[4][DD * ST2];   // per-warp transposed member cache
    __shared__ float s_pp[4][CAP2];
    __shared__ float s_a[4][CAP2];
    __shared__ float s_mu[4][DD];
    __shared__ int   s_lst[4][CAP2];

    int w    = threadIdx.x >> 5;
    int lane = threadIdx.x & 31;
    int i    = blockIdx.x * 4 + w;

    float c  = fabsf(*cph) + 1e-6f;
    float sc = sqrtf(c);
    float maxn = (1.0f - 1e-5f) / sc;

    // ---- decode row bitmask ----
    unsigned myword = (lane < 16) ? g_rowbits[i * 16 + lane] : 0u;
    int pc = __popc(myword);
    int incl = pc;
    #pragma unroll
    for (int o = 1; o < 32; o <<= 1) {
        int vv = __shfl_up_sync(FULL, incl, o);
        if (lane >= o) incl += vv;
    }
    int excl = incl - pc;
    int cnt  = __shfl_sync(FULL, incl, 15);
    bool cache = (cnt <= CAP2);
    float cntf = (float)cnt;

    if (cache && lane < 16) {
        unsigned word = myword;
        int off  = excl;
        int base = lane * 32;
        while (word) {
            s_lst[w][off++] = base + __ffs(word) - 1;
            word &= word - 1;
        }
    }
    __syncwarp();

    // prologue: linear sums + cache
    float sp = 0.f, sl = 0.f, se = 0.f, sm = 0.f;
    if (cache) {
        for (int j = 0; j < cnt; j++) {
            int g = s_lst[w][j];
            float p = g_es[g * DD + lane];
            sp += p;
            sl += g_elamx[g * DD + lane];
            se += g_ee[g * DD + lane];
            sm += g_elamm1[g];
            s_pT[w][lane * ST2 + j] = p;
            if (lane == 0) s_pp[w][j] = g_esn2[g];
        }
    } else {
        for (int wd = 0; wd < 16; wd++) {
            unsigned word = g_rowbits[i * 16 + wd];
            while (word) {
                int g = wd * 32 + __ffs(word) - 1;
                word &= word - 1;
                sp += g_es[g * DD + lane];
                sl += g_elamx[g * DD + lane];
                se += g_ee[g * DD + lane];
                sm += g_elamm1[g];
            }
        }
    }

    float oe = se / fmaxf(cntf, 1e-6f);

    // gyromidpoint + final hyp_project
    float den = fmaxf(sm, 1e-6f);
    float y   = sl / den;
    float yn  = fmaxf(sqrtf(wsum(y * y)), 1e-6f);
    float arg = clip1(sc * yn);
    float oh  = tanhf(0.5f * atanhf(arg)) * y / (sc * yn);
    float n   = sqrtf(wsum(oh * oh));
    float nm  = fmaxf(n, 1e-6f);
    if (nm > maxn) oh *= maxn / nm;

    // sphere midpoint
    float mu = sp / cntf;
    mu /= fmaxf(sqrtf(wsum(mu * mu)), 1e-6f);

    if (cache) {
        s_mu[w][lane] = mu;
        __syncwarp();
        for (int it = 0; it < 5; it++) {
            // (1) lane = member: dots, no shuffles
            float asum_d = 0.f, asum_r = 0.f;
            for (int m = lane; m < cnt; m += 32) {
                float d0 = 0.f, d1 = 0.f;
                #pragma unroll
                for (int d = 0; d < DD; d += 2) {
                    d0 = fmaf(s_mu[w][d],     s_pT[w][d * ST2 + m],       d0);
                    d1 = fmaf(s_mu[w][d + 1], s_pT[w][(d + 1) * ST2 + m], d1);
                }
                float draw = d0 + d1;
                float dotc = clip1(draw);
                float theta = acosf(dotc);
                float dn2 = s_pp[w][m] - dotc * (2.0f * draw - dotc);  // mm = 1
                float dn  = fmaxf(sqrtf(fmaxf(dn2, 0.f)), 1e-6f);
                float a   = theta / dn;
                s_a[w][m] = a;
                asum_d = fmaf(a, dotc, asum_d);
                asum_r = fmaf(a, draw, asum_r);
            }
            __syncwarp();
            float bt = wsum(asum_d);
            float br = wsum(asum_r);
            // (2) lane = dim accumulation
            float t0 = 0.f, t1 = 0.f;
            int m = 0;
            for (; m + 1 < cnt; m += 2) {
                t0 = fmaf(s_a[w][m],     s_pT[w][lane * ST2 + m],     t0);
                t1 = fmaf(s_a[w][m + 1], s_pT[w][lane * ST2 + m + 1], t1);
            }
            if (m < cnt) t0 = fmaf(s_a[w][m], s_pT[w][lane * ST2 + m], t0);
            float mul = s_mu[w][lane];
            float t = fmaf(-bt, mul, t0 + t1);
            float avg = t / cntf;
            float vn2 = wsum(avg * avg);
            float vn  = sqrtf(vn2);
            float vns = fmaxf(vn, 1e-6f);
            float cv = cosf(vn), sv = sinf(vn);
            float mudotavg = (br - bt) / cntf;
            float r   = cv * mul + sv * avg / vns;
            float svv = sv / vns;
            float rn2 = fmaf(cv * cv, 1.0f, fmaf(2.0f * cv * svv, mudotavg, svv * svv * vn2));
            float rn  = fmaxf(sqrtf(rn2), 1e-6f);
            mul = r / rn;
            s_mu[w][lane] = mul;
            __syncwarp();
        }
        mu = s_mu[w][lane];
    } else {
        // fallback: shuffle-based path over row bits (rare)
        for (int it = 0; it < 5; it++) {
            float mm = wsum(mu * mu);
            float t = 0.f, bsum = 0.f;
            for (int wd = 0; wd < 16; wd++) {
                unsigned word = g_rowbits[i * 16 + wd];
                while (word) {
                    int g0 = wd * 32 + __ffs(word) - 1;
                    word &= word - 1;
                    float p0 = g_es[g0 * DD + lane];
                    float w0 = wsum(mu * p0);
                    float dc0 = clip1(w0);
                    float th0 = acosf(dc0);
                    float q0 = g_esn2[g0] - dc0 * (2.0f * w0 - dc0 * mm);
                    float a0 = th0 / fmaxf(sqrtf(fmaxf(q0, 0.f)), 1e-6f);
                    t    = fmaf(a0, p0, t);
                    bsum = fmaf(-a0, dc0, bsum);
                }
            }
            t = fmaf(bsum, mu, t);
            t /= cntf;
            float vn  = sqrtf(wsum(t * t));
            float vns = fmaxf(vn, 1e-6f);
            mu = cosf(vn) * mu + sinf(vn) * t / vns;
            mu /= fmaxf(sqrtf(wsum(mu * mu)), 1e-6f);
        }
    }
    float os = mu / fmaxf(sqrtf(wsum(mu * mu)), 1e-6f);

    out[i * 96 + lane]      = oh;
    out[i * 96 + 32 + lane] = os;
    out[i * 96 + 64 + lane] = oe;
}

// ---------------- launch ----------------
extern "C" void kernel_launch(void* const* d_in, const int* in_sizes, int n_in,
                              void* d_out, int out_size) {
    const float* x   = (const float*)d_in[0];
    const float* H   = (const float*)d_in[1];
    const float* Wh  = (const float*)d_in[2];
    const float* bh  = (const float*)d_in[3];
    const float* Ws  = (const float*)d_in[4];
    const float* bs  = (const float*)d_in[5];
    const float* We  = (const float*)d_in[6];
    const float* be  = (const float*)d_in[7];
    const float* c_h = (const float*)d_in[8];
    float* out = (float*)d_out;

    k_pre<<<PRE_BLOCKS, 256>>>(x, H, Wh, bh, Ws, bs, We, be, c_h);
    k_agg1<<<MM, BK>>>(c_h);
    k_agg2<<<NN / 4, 128>>>(out, c_h);
}